// round 13
// baseline (speedup 1.0000x reference)
#include <cuda_runtime.h>
#include <cuda_bf16.h>
#include <cstdint>

#define N_NODES 50000
#define N_EDGES 1600000
#define DIM     128
#define N_LAYERS 4
#define N_GRAPHS 512
#define M_TILES  391            // ceil(50000/128)
#define M_PAD    (M_TILES*128)  // 50048
#define SCAN_BLOCKS 49          // 49*1024 >= 50000
#define N_CHUNKS 4
#define TILES_PER_CHUNK 98      // 98+98+98+97 = 391
#define ROWS_PER_CHUNK (TILES_PER_CHUNK * 128)   // 12544

typedef unsigned long long ull;

// ---------------- scratch (static device globals; no allocation) -------------
__device__ int   g_deg[N_NODES];
__device__ int   g_rowstart[N_NODES + 1];
__device__ int   g_cursor[N_NODES];
__device__ int   g_bsum[SCAN_BLOCKS];
__device__ int   g_csr[N_EDGES];
__device__ float g_hin[M_PAD * DIM];   // x + agg (rows >= N_NODES stay 0 forever)
__device__ float g_xbuf[M_PAD * DIM];  // layer output ping
__device__ float g_ybuf[M_PAD * DIM];  // layer output pong

// ---------------- streams/events (created before main -> in mem baseline) ----
struct StreamInit {
    cudaStream_t sB = nullptr;
    cudaEvent_t evA[N_LAYERS][N_CHUNKS];
    cudaEvent_t evB[N_LAYERS];
    bool ok = false;
    StreamInit() {
        if (cudaStreamCreateWithFlags(&sB, cudaStreamNonBlocking) != cudaSuccess) return;
        for (int l = 0; l < N_LAYERS; l++) {
            for (int c = 0; c < N_CHUNKS; c++)
                if (cudaEventCreateWithFlags(&evA[l][c], cudaEventDisableTiming) != cudaSuccess) return;
            if (cudaEventCreateWithFlags(&evB[l], cudaEventDisableTiming) != cudaSuccess) return;
        }
        ok = true;
    }
};
static StreamInit g_si;

// ---------------- packed fp32x2 FMA (Blackwell FFMA2) ------------------------
__device__ __forceinline__ ull ffma2(ull a, ull b, ull c) {
    ull d;
    asm("fma.rn.f32x2 %0, %1, %2, %3;" : "=l"(d) : "l"(a), "l"(b), "l"(c));
    return d;
}
__device__ __forceinline__ ull dup2(float f) {
    ull d;
    asm("mov.b64 %0, {%1, %1};" : "=l"(d) : "f"(f));
    return d;
}
__device__ __forceinline__ ull pack2(float lo, float hi) {
    ull d;
    asm("mov.b64 %0, {%1, %2};" : "=l"(d) : "f"(lo), "f"(hi));
    return d;
}

// ---------------- CSR build --------------------------------------------------
__global__ void k_hist(const int* __restrict__ ei) {
    int t = blockIdx.x * blockDim.x + threadIdx.x;
    if (t < N_EDGES / 4) {
        int4 d = ((const int4*)(ei + N_EDGES))[t];
        atomicAdd(&g_deg[d.x], 1);
        atomicAdd(&g_deg[d.y], 1);
        atomicAdd(&g_deg[d.z], 1);
        atomicAdd(&g_deg[d.w], 1);
    }
}

__global__ void k_scan_part() {
    __shared__ int sh[1024];
    int t = threadIdx.x;
    int i = blockIdx.x * 1024 + t;
    int v = (i < N_NODES) ? g_deg[i] : 0;
    sh[t] = v;
    __syncthreads();
    #pragma unroll
    for (int off = 1; off < 1024; off <<= 1) {
        int u = (t >= off) ? sh[t - off] : 0;
        __syncthreads();
        sh[t] += u;
        __syncthreads();
    }
    if (i < N_NODES) g_rowstart[i] = sh[t] - v;   // local exclusive
    if (t == 1023) g_bsum[blockIdx.x] = sh[1023];
}

__global__ void k_scan_add() {
    __shared__ int sb[SCAN_BLOCKS];
    __shared__ int s_total;
    int t = threadIdx.x;
    if (t < SCAN_BLOCKS) sb[t] = g_bsum[t];
    __syncthreads();
    if (t == 0) {
        int run = 0;
        #pragma unroll 1
        for (int i = 0; i < SCAN_BLOCKS; i++) { int v = sb[i]; sb[i] = run; run += v; }
        s_total = run;
    }
    __syncthreads();
    int off = sb[blockIdx.x];
    int i = blockIdx.x * 1024 + t;
    if (i < N_NODES) {
        int r = g_rowstart[i] + off;
        g_rowstart[i] = r;
        g_cursor[i]   = r;
    }
    if (blockIdx.x == 0 && t == 0) g_rowstart[N_NODES] = s_total;
}

__global__ void k_scatter(const int* __restrict__ ei) {
    int t = blockIdx.x * blockDim.x + threadIdx.x;
    if (t < N_EDGES / 4) {
        int4 s = ((const int4*)ei)[t];
        int4 d = ((const int4*)(ei + N_EDGES))[t];
        g_csr[atomicAdd(&g_cursor[d.x], 1)] = s.x;
        g_csr[atomicAdd(&g_cursor[d.y], 1)] = s.y;
        g_csr[atomicAdd(&g_cursor[d.z], 1)] = s.z;
        g_csr[atomicAdd(&g_cursor[d.w], 1)] = s.w;
    }
}

// ---------------- aggregation over node range [node_base, node_end) ----------
__global__ void k_agg(const float* __restrict__ xin, float* __restrict__ hout,
                      int node_base, int node_end) {
    int warp = node_base + ((blockIdx.x * blockDim.x + threadIdx.x) >> 5);
    int lane = threadIdx.x & 31;
    if (warp >= node_end) return;
    const float4* x4 = (const float4*)xin;
    float4 acc = x4[(size_t)warp * 32 + lane];
    int s = g_rowstart[warp];
    int e = g_rowstart[warp + 1];
    int j = s;
    for (; j + 8 <= e; j += 8) {
        int idx[8];
        #pragma unroll
        for (int t = 0; t < 8; t++) idx[t] = __ldg(&g_csr[j + t]);
        float4 v[8];
        #pragma unroll
        for (int t = 0; t < 8; t++) v[t] = __ldg(&x4[(size_t)idx[t] * 32 + lane]);
        #pragma unroll
        for (int t = 0; t < 8; t++) {
            acc.x += v[t].x; acc.y += v[t].y; acc.z += v[t].z; acc.w += v[t].w;
        }
    }
    for (; j < e; j++) {
        int src = __ldg(&g_csr[j]);
        float4 v = __ldg(&x4[(size_t)src * 32 + lane]);
        acc.x += v.x; acc.y += v.y; acc.z += v.z; acc.w += v.w;
    }
    ((float4*)hout)[(size_t)warp * 32 + lane] = acc;
}

// ---------------- fused MLP: C = relu(A@W1+b1)@W2 + b2 ----------------------
#define W_STRIDE  160
#define A2_STRIDE 132
#define H_STRIDE  130
#define WT_FLOATS (16 * W_STRIDE)        // 2560
#define A2_ULLS   (16 * A2_STRIDE)       // 2112
#define OFF_A2f   WT_FLOATS
#define OFF_Hf    (WT_FLOATS + A2_ULLS * 2)
#define MLP_SMEM  ((OFF_Hf + 128 * H_STRIDE) * 4)   // 93,696 B

__device__ __forceinline__ int widx(int c) { return c + ((c >> 3) << 1); }

__global__ __launch_bounds__(256, 2) void k_mlp(const float* __restrict__ A,
                                                const float* __restrict__ W1,
                                                const float* __restrict__ b1,
                                                const float* __restrict__ W2,
                                                const float* __restrict__ b2,
                                                int tile_base,
                                                float* __restrict__ C) {
    extern __shared__ __align__(16) float smem[];
    float* sW  = smem;
    ull*   sA2 = (ull*)(smem + OFF_A2f);
    float* sH  = smem + OFF_Hf;

    const int tid  = threadIdx.x;
    const int row0 = (tile_base + blockIdx.x) * 128;
    const int tr = tid >> 4;
    const int tc = tid & 15;
    const int rbase = tr * 8;
    const int cbase = tc * 8;

    const int wk0 = (tid * 2) >> 5,       wc0 = ((tid * 2) & 31) * 4;
    const int wk1 = (tid * 2 + 1) >> 5,   wc1 = ((tid * 2 + 1) & 31) * 4;
    const int ar0 = (tid * 2) >> 2,       akc0 = ((tid * 2) & 3) * 4;
    const int ar1 = (tid * 2 + 1) >> 2,   akc1 = ((tid * 2 + 1) & 3) * 4;

    ull acc[8][4];

    // ===================== GEMM1: sH = relu(A@W1 + b1) =======================
    #pragma unroll
    for (int i = 0; i < 8; i++)
        #pragma unroll
        for (int j = 0; j < 4; j++) acc[i][j] = 0ULL;

    float4 wpf0 = *(const float4*)&W1[(size_t)wk0 * DIM + wc0];
    float4 wpf1 = *(const float4*)&W1[(size_t)wk1 * DIM + wc1];
    float4 apf0 = *(const float4*)&A[(size_t)(row0 + ar0) * DIM + akc0];
    float4 apf1 = *(const float4*)&A[(size_t)(row0 + ar1) * DIM + akc1];

    #pragma unroll 1
    for (int k0i = 0; k0i < 8; k0i++) {
        if (k0i > 0) __syncthreads();
        {
            float* d0 = &sW[wk0 * W_STRIDE + widx(wc0)];
            d0[0] = wpf0.x; d0[1] = wpf0.y; d0[2] = wpf0.z; d0[3] = wpf0.w;
            float* d1 = &sW[wk1 * W_STRIDE + widx(wc1)];
            d1[0] = wpf1.x; d1[1] = wpf1.y; d1[2] = wpf1.z; d1[3] = wpf1.w;
            sA2[(akc0 + 0) * A2_STRIDE + ar0] = dup2(apf0.x);
            sA2[(akc0 + 1) * A2_STRIDE + ar0] = dup2(apf0.y);
            sA2[(akc0 + 2) * A2_STRIDE + ar0] = dup2(apf0.z);
            sA2[(akc0 + 3) * A2_STRIDE + ar0] = dup2(apf0.w);
            sA2[(akc1 + 0) * A2_STRIDE + ar1] = dup2(apf1.x);
            sA2[(akc1 + 1) * A2_STRIDE + ar1] = dup2(apf1.y);
            sA2[(akc1 + 2) * A2_STRIDE + ar1] = dup2(apf1.z);
            sA2[(akc1 + 3) * A2_STRIDE + ar1] = dup2(apf1.w);
        }
        __syncthreads();
        if (k0i < 7) {
            const int nk0 = (k0i + 1) * 16;
            wpf0 = *(const float4*)&W1[(size_t)(nk0 + wk0) * DIM + wc0];
            wpf1 = *(const float4*)&W1[(size_t)(nk0 + wk1) * DIM + wc1];
            apf0 = *(const float4*)&A[(size_t)(row0 + ar0) * DIM + nk0 + akc0];
            apf1 = *(const float4*)&A[(size_t)(row0 + ar1) * DIM + nk0 + akc1];
        }
        #pragma unroll
        for (int kk = 0; kk < 16; kk++) {
            ull b2v[4];
            const float* wrow = &sW[kk * W_STRIDE + 10 * tc];
            #pragma unroll
            for (int j = 0; j < 4; j++) b2v[j] = *(const ull*)&wrow[2 * j];
            ull a2[8];
            const ull* arow = &sA2[kk * A2_STRIDE + rbase];
            #pragma unroll
            for (int i = 0; i < 8; i++) a2[i] = arow[i];
            #pragma unroll
            for (int i = 0; i < 8; i++)
                #pragma unroll
                for (int j = 0; j < 4; j++)
                    acc[i][j] = ffma2(a2[i], b2v[j], acc[i][j]);
        }
    }

    {
        float bv[8];
        #pragma unroll
        for (int j = 0; j < 8; j++) bv[j] = b1[cbase + j];
        #pragma unroll
        for (int i = 0; i < 8; i++) {
            ull* dst = (ull*)&sH[(rbase + i) * H_STRIDE + cbase];
            #pragma unroll
            for (int j = 0; j < 4; j++) {
                ull v = acc[i][j];
                float lo = fmaxf(__uint_as_float((unsigned)v)         + bv[2 * j],     0.f);
                float hi = fmaxf(__uint_as_float((unsigned)(v >> 32)) + bv[2 * j + 1], 0.f);
                dst[j] = pack2(lo, hi);
            }
        }
    }
    wpf0 = *(const float4*)&W2[(size_t)wk0 * DIM + wc0];
    wpf1 = *(const float4*)&W2[(size_t)wk1 * DIM + wc1];
    __syncthreads();

    // ===================== GEMM2: C = sH@W2 + b2 =============================
    #pragma unroll
    for (int i = 0; i < 8; i++)
        #pragma unroll
        for (int j = 0; j < 4; j++) acc[i][j] = 0ULL;

    #pragma unroll 1
    for (int k0i = 0; k0i < 8; k0i++) {
        const int k0 = k0i * 16;
        if (k0i > 0) __syncthreads();
        {
            float* d0 = &sW[wk0 * W_STRIDE + widx(wc0)];
            d0[0] = wpf0.x; d0[1] = wpf0.y; d0[2] = wpf0.z; d0[3] = wpf0.w;
            float* d1 = &sW[wk1 * W_STRIDE + widx(wc1)];
            d1[0] = wpf1.x; d1[1] = wpf1.y; d1[2] = wpf1.z; d1[3] = wpf1.w;
            #pragma unroll
            for (int i = 0; i < 8; i++) {
                int e  = tid + i * 256;
                int kk = e >> 7;
                int r  = e & 127;
                sA2[kk * A2_STRIDE + r] = dup2(sH[r * H_STRIDE + k0 + kk]);
            }
        }
        __syncthreads();
        if (k0i < 7) {
            const int nk0 = k0 + 16;
            wpf0 = *(const float4*)&W2[(size_t)(nk0 + wk0) * DIM + wc0];
            wpf1 = *(const float4*)&W2[(size_t)(nk0 + wk1) * DIM + wc1];
        }
        #pragma unroll
        for (int kk = 0; kk < 16; kk++) {
            ull b2v[4];
            const float* wrow = &sW[kk * W_STRIDE + 10 * tc];
            #pragma unroll
            for (int j = 0; j < 4; j++) b2v[j] = *(const ull*)&wrow[2 * j];
            ull a2[8];
            const ull* arow = &sA2[kk * A2_STRIDE + rbase];
            #pragma unroll
            for (int i = 0; i < 8; i++) a2[i] = arow[i];
            #pragma unroll
            for (int i = 0; i < 8; i++)
                #pragma unroll
                for (int j = 0; j < 4; j++)
                    acc[i][j] = ffma2(a2[i], b2v[j], acc[i][j]);
        }
    }

    {
        float bv[8];
        #pragma unroll
        for (int j = 0; j < 8; j++) bv[j] = b2[cbase + j];
        #pragma unroll
        for (int i = 0; i < 8; i++) {
            int r = row0 + rbase + i;
            if (r < N_NODES) {
                float o[8];
                #pragma unroll
                for (int j = 0; j < 4; j++) {
                    ull v = acc[i][j];
                    o[2 * j]     = __uint_as_float((unsigned)v)         + bv[2 * j];
                    o[2 * j + 1] = __uint_as_float((unsigned)(v >> 32)) + bv[2 * j + 1];
                }
                *(float4*)&C[(size_t)r * DIM + cbase]     = make_float4(o[0], o[1], o[2], o[3]);
                *(float4*)&C[(size_t)r * DIM + cbase + 4] = make_float4(o[4], o[5], o[6], o[7]);
            }
        }
    }
}

// ---------------- pooling: batch is sorted -> one block per graph ------------
__global__ void k_pool(const float* __restrict__ x,
                       const int* __restrict__ batch,
                       float* __restrict__ out) {
    int g = blockIdx.x;
    int c = threadIdx.x;
    int a = 0, b = N_NODES;
    while (a < b) { int m = (a + b) >> 1; if (batch[m] < g) a = m + 1; else b = m; }
    int lo = a;
    b = N_NODES;
    while (a < b) { int m = (a + b) >> 1; if (batch[m] < g + 1) a = m + 1; else b = m; }
    int hi = a;
    float s0 = 0.f, s1 = 0.f, s2 = 0.f, s3 = 0.f;
    int i = lo;
    for (; i + 4 <= hi; i += 4) {
        s0 += x[(size_t)(i + 0) * DIM + c];
        s1 += x[(size_t)(i + 1) * DIM + c];
        s2 += x[(size_t)(i + 2) * DIM + c];
        s3 += x[(size_t)(i + 3) * DIM + c];
    }
    for (; i < hi; i++) s0 += x[(size_t)i * DIM + c];
    out[(size_t)g * DIM + c] = (s0 + s1) + (s2 + s3);
}

// ---------------- launch -----------------------------------------------------
extern "C" void kernel_launch(void* const* d_in, const int* in_sizes, int n_in,
                              void* d_out, int out_size) {
    const float* x   = (const float*)d_in[0];
    const int* ei    = (const int*)d_in[1];   // int32 (JAX x64 disabled)
    const int* bat   = (const int*)d_in[2];   // int32
    const float* Ws1 = (const float*)d_in[3];
    const float* bs1 = (const float*)d_in[4];
    const float* Ws2 = (const float*)d_in[5];
    const float* bs2 = (const float*)d_in[6];
    float* out       = (float*)d_out;

    void* p;
    cudaGetSymbolAddress(&p, g_hin);  float* hin = (float*)p;
    cudaGetSymbolAddress(&p, g_xbuf); float* xb  = (float*)p;
    cudaGetSymbolAddress(&p, g_ybuf); float* yb  = (float*)p;
    cudaGetSymbolAddress(&p, g_deg);
    cudaMemsetAsync(p, 0, N_NODES * sizeof(int));

    cudaFuncSetAttribute(k_mlp, cudaFuncAttributeMaxDynamicSharedMemorySize, MLP_SMEM);

    k_hist<<<(N_EDGES / 4 + 255) / 256, 256>>>(ei);
    k_scan_part<<<SCAN_BLOCKS, 1024>>>();
    k_scan_add<<<SCAN_BLOCKS, 1024>>>();
    k_scatter<<<(N_EDGES / 4 + 255) / 256, 256>>>(ei);

    const bool pipelined = g_si.ok;

    // ping-pong: layer l reads src, writes dst (dst != src) so the overlapped
    // k_mlp never clobbers rows that k_agg of the same layer still gathers.
    const float* src = x;
    float* dst = xb;
    for (int l = 0; l < N_LAYERS; l++) {
        const float* W1 = Ws1 + (size_t)l * DIM * DIM;
        const float* B1 = bs1 + (size_t)l * DIM;
        const float* W2 = Ws2 + (size_t)l * DIM * DIM;
        const float* B2 = bs2 + (size_t)l * DIM;

        if (pipelined) {
            for (int c = 0; c < N_CHUNKS; c++) {
                int nb = c * ROWS_PER_CHUNK;
                int ne = (c == N_CHUNKS - 1) ? N_NODES : nb + ROWS_PER_CHUNK;
                int blocks = ((ne - nb) * 32 + 255) / 256;
                k_agg<<<blocks, 256>>>(src, hin, nb, ne);
                cudaEventRecord(g_si.evA[l][c], 0);
            }
            for (int c = 0; c < N_CHUNKS; c++) {
                int tb = c * TILES_PER_CHUNK;
                int tn = (c == N_CHUNKS - 1) ? (M_TILES - tb) : TILES_PER_CHUNK;
                cudaStreamWaitEvent(g_si.sB, g_si.evA[l][c], 0);
                k_mlp<<<tn, 256, MLP_SMEM, g_si.sB>>>(hin, W1, B1, W2, B2, tb, dst);
            }
            cudaEventRecord(g_si.evB[l], g_si.sB);
            cudaStreamWaitEvent(0, g_si.evB[l], 0);
        } else {
            int blocks = (N_NODES * 32 + 255) / 256;
            k_agg<<<blocks, 256>>>(src, hin, 0, N_NODES);
            k_mlp<<<M_TILES, 256, MLP_SMEM>>>(hin, W1, B1, W2, B2, 0, dst);
        }
        src = dst;
        dst = (dst == xb) ? yb : xb;
    }
    k_pool<<<N_GRAPHS, DIM>>>(src, bat, out);
}

// round 14
// speedup vs baseline: 1.4053x; 1.4053x over previous
#include <cuda_runtime.h>
#include <cuda_bf16.h>
#include <cstdint>

#define N_NODES 50000
#define N_EDGES 1600000
#define DIM     128
#define N_LAYERS 4
#define N_GRAPHS 512
#define M_TILES  391            // ceil(50000/128)
#define M_PAD    (M_TILES*128)  // 50048
#define SCAN_BLOCKS 49          // 49*1024 >= 50000
#define MLP_GRID 296            // 148 SMs * 2 blocks/SM, persistent

typedef unsigned long long ull;

// ---------------- scratch (static device globals; no allocation) -------------
__device__ int   g_deg[N_NODES];
__device__ int   g_rowstart[N_NODES + 1];
__device__ int   g_cursor[N_NODES];
__device__ int   g_bsum[SCAN_BLOCKS];
__device__ int   g_csr[N_EDGES];
__device__ float g_hin[M_PAD * DIM];   // x + agg (rows >= N_NODES stay 0 forever)
__device__ float g_xbuf[M_PAD * DIM];  // layer output

// ---------------- packed fp32x2 FMA (Blackwell FFMA2) ------------------------
__device__ __forceinline__ ull ffma2(ull a, ull b, ull c) {
    ull d;
    asm("fma.rn.f32x2 %0, %1, %2, %3;" : "=l"(d) : "l"(a), "l"(b), "l"(c));
    return d;
}
__device__ __forceinline__ ull dup2(float f) {
    ull d;
    asm("mov.b64 %0, {%1, %1};" : "=l"(d) : "f"(f));
    return d;
}
__device__ __forceinline__ ull pack2(float lo, float hi) {
    ull d;
    asm("mov.b64 %0, {%1, %2};" : "=l"(d) : "f"(lo), "f"(hi));
    return d;
}

// ---------------- CSR build --------------------------------------------------
__global__ void k_hist(const int* __restrict__ ei) {
    int t = blockIdx.x * blockDim.x + threadIdx.x;
    if (t < N_EDGES / 4) {
        int4 d = ((const int4*)(ei + N_EDGES))[t];
        atomicAdd(&g_deg[d.x], 1);
        atomicAdd(&g_deg[d.y], 1);
        atomicAdd(&g_deg[d.z], 1);
        atomicAdd(&g_deg[d.w], 1);
    }
}

__global__ void k_scan_part() {
    __shared__ int sh[1024];
    int t = threadIdx.x;
    int i = blockIdx.x * 1024 + t;
    int v = (i < N_NODES) ? g_deg[i] : 0;
    sh[t] = v;
    __syncthreads();
    #pragma unroll
    for (int off = 1; off < 1024; off <<= 1) {
        int u = (t >= off) ? sh[t - off] : 0;
        __syncthreads();
        sh[t] += u;
        __syncthreads();
    }
    if (i < N_NODES) g_rowstart[i] = sh[t] - v;   // local exclusive
    if (t == 1023) g_bsum[blockIdx.x] = sh[1023];
}

__global__ void k_scan_add() {
    __shared__ int sb[SCAN_BLOCKS];
    __shared__ int s_total;
    int t = threadIdx.x;
    if (t < SCAN_BLOCKS) sb[t] = g_bsum[t];
    __syncthreads();
    if (t == 0) {
        int run = 0;
        #pragma unroll 1
        for (int i = 0; i < SCAN_BLOCKS; i++) { int v = sb[i]; sb[i] = run; run += v; }
        s_total = run;
    }
    __syncthreads();
    int off = sb[blockIdx.x];
    int i = blockIdx.x * 1024 + t;
    if (i < N_NODES) {
        int r = g_rowstart[i] + off;
        g_rowstart[i] = r;
        g_cursor[i]   = r;
    }
    if (blockIdx.x == 0 && t == 0) g_rowstart[N_NODES] = s_total;
}

__global__ void k_scatter(const int* __restrict__ ei) {
    int t = blockIdx.x * blockDim.x + threadIdx.x;
    if (t < N_EDGES / 4) {
        int4 s = ((const int4*)ei)[t];
        int4 d = ((const int4*)(ei + N_EDGES))[t];
        g_csr[atomicAdd(&g_cursor[d.x], 1)] = s.x;
        g_csr[atomicAdd(&g_cursor[d.y], 1)] = s.y;
        g_csr[atomicAdd(&g_cursor[d.z], 1)] = s.z;
        g_csr[atomicAdd(&g_cursor[d.w], 1)] = s.w;
    }
}

// ---------------- aggregation: hout[n] = xin[n] + sum_{s in N(n)} xin[s] -----
// 64-thread blocks (2 warps): finer retirement granularity -> smaller tail
__global__ __launch_bounds__(64) void k_agg(const float* __restrict__ xin,
                                            float* __restrict__ hout) {
    int warp = (blockIdx.x * blockDim.x + threadIdx.x) >> 5;
    int lane = threadIdx.x & 31;
    if (warp >= N_NODES) return;
    const float4* x4 = (const float4*)xin;
    float4 acc = x4[(size_t)warp * 32 + lane];
    int s = g_rowstart[warp];
    int e = g_rowstart[warp + 1];
    int j = s;
    for (; j + 8 <= e; j += 8) {
        int idx[8];
        #pragma unroll
        for (int t = 0; t < 8; t++) idx[t] = __ldg(&g_csr[j + t]);
        float4 v[8];
        #pragma unroll
        for (int t = 0; t < 8; t++) v[t] = __ldg(&x4[(size_t)idx[t] * 32 + lane]);
        #pragma unroll
        for (int t = 0; t < 8; t++) {
            acc.x += v[t].x; acc.y += v[t].y; acc.z += v[t].z; acc.w += v[t].w;
        }
    }
    for (; j < e; j++) {
        int src = __ldg(&g_csr[j]);
        float4 v = __ldg(&x4[(size_t)src * 32 + lane]);
        acc.x += v.x; acc.y += v.y; acc.z += v.z; acc.w += v.w;
    }
    ((float4*)hout)[(size_t)warp * 32 + lane] = acc;
}

// ---------------- fused MLP (persistent): C = relu(A@W1+b1)@W2 + b2 ---------
#define W_STRIDE  160
#define A2_STRIDE 132
#define H_STRIDE  130
#define WT_FLOATS (16 * W_STRIDE)        // 2560
#define A2_ULLS   (16 * A2_STRIDE)       // 2112
#define OFF_A2f   WT_FLOATS
#define OFF_Hf    (WT_FLOATS + A2_ULLS * 2)
#define MLP_SMEM  ((OFF_Hf + 128 * H_STRIDE) * 4)   // 93,696 B

__device__ __forceinline__ int widx(int c) { return c + ((c >> 3) << 1); }

__global__ __launch_bounds__(256, 2) void k_mlp(const float* __restrict__ A,
                                                const float* __restrict__ W1,
                                                const float* __restrict__ b1,
                                                const float* __restrict__ W2,
                                                const float* __restrict__ b2,
                                                float* __restrict__ C) {
    extern __shared__ __align__(16) float smem[];
    float* sW  = smem;
    ull*   sA2 = (ull*)(smem + OFF_A2f);
    float* sH  = smem + OFF_Hf;

    const int tid  = threadIdx.x;
    const int tr = tid >> 4;
    const int tc = tid & 15;
    const int rbase = tr * 8;
    const int cbase = tc * 8;

    const int wk0 = (tid * 2) >> 5,       wc0 = ((tid * 2) & 31) * 4;
    const int wk1 = (tid * 2 + 1) >> 5,   wc1 = ((tid * 2 + 1) & 31) * 4;
    const int ar0 = (tid * 2) >> 2,       akc0 = ((tid * 2) & 3) * 4;
    const int ar1 = (tid * 2 + 1) >> 2,   akc1 = ((tid * 2 + 1) & 3) * 4;

    // persistent loop over tiles
    for (int tile = blockIdx.x; tile < M_TILES; tile += gridDim.x) {
        const int row0 = tile * 128;
        ull acc[8][4];

        // ================= GEMM1: sH = relu(A@W1 + b1) =======================
        #pragma unroll
        for (int i = 0; i < 8; i++)
            #pragma unroll
            for (int j = 0; j < 4; j++) acc[i][j] = 0ULL;

        float4 wpf0 = *(const float4*)&W1[(size_t)wk0 * DIM + wc0];
        float4 wpf1 = *(const float4*)&W1[(size_t)wk1 * DIM + wc1];
        float4 apf0 = *(const float4*)&A[(size_t)(row0 + ar0) * DIM + akc0];
        float4 apf1 = *(const float4*)&A[(size_t)(row0 + ar1) * DIM + akc1];

        #pragma unroll 1
        for (int k0i = 0; k0i < 8; k0i++) {
            __syncthreads();   // prior compute (this tile or previous tile) done
            {
                float* d0 = &sW[wk0 * W_STRIDE + widx(wc0)];
                d0[0] = wpf0.x; d0[1] = wpf0.y; d0[2] = wpf0.z; d0[3] = wpf0.w;
                float* d1 = &sW[wk1 * W_STRIDE + widx(wc1)];
                d1[0] = wpf1.x; d1[1] = wpf1.y; d1[2] = wpf1.z; d1[3] = wpf1.w;
                sA2[(akc0 + 0) * A2_STRIDE + ar0] = dup2(apf0.x);
                sA2[(akc0 + 1) * A2_STRIDE + ar0] = dup2(apf0.y);
                sA2[(akc0 + 2) * A2_STRIDE + ar0] = dup2(apf0.z);
                sA2[(akc0 + 3) * A2_STRIDE + ar0] = dup2(apf0.w);
                sA2[(akc1 + 0) * A2_STRIDE + ar1] = dup2(apf1.x);
                sA2[(akc1 + 1) * A2_STRIDE + ar1] = dup2(apf1.y);
                sA2[(akc1 + 2) * A2_STRIDE + ar1] = dup2(apf1.z);
                sA2[(akc1 + 3) * A2_STRIDE + ar1] = dup2(apf1.w);
            }
            __syncthreads();
            if (k0i < 7) {
                const int nk0 = (k0i + 1) * 16;
                wpf0 = *(const float4*)&W1[(size_t)(nk0 + wk0) * DIM + wc0];
                wpf1 = *(const float4*)&W1[(size_t)(nk0 + wk1) * DIM + wc1];
                apf0 = *(const float4*)&A[(size_t)(row0 + ar0) * DIM + nk0 + akc0];
                apf1 = *(const float4*)&A[(size_t)(row0 + ar1) * DIM + nk0 + akc1];
            }
            #pragma unroll
            for (int kk = 0; kk < 16; kk++) {
                ull b2v[4];
                const float* wrow = &sW[kk * W_STRIDE + 10 * tc];
                #pragma unroll
                for (int j = 0; j < 4; j++) b2v[j] = *(const ull*)&wrow[2 * j];
                ull a2[8];
                const ull* arow = &sA2[kk * A2_STRIDE + rbase];
                #pragma unroll
                for (int i = 0; i < 8; i++) a2[i] = arow[i];
                #pragma unroll
                for (int i = 0; i < 8; i++)
                    #pragma unroll
                    for (int j = 0; j < 4; j++)
                        acc[i][j] = ffma2(a2[i], b2v[j], acc[i][j]);
            }
        }

        {
            float bv[8];
            #pragma unroll
            for (int j = 0; j < 8; j++) bv[j] = b1[cbase + j];
            #pragma unroll
            for (int i = 0; i < 8; i++) {
                ull* dst = (ull*)&sH[(rbase + i) * H_STRIDE + cbase];
                #pragma unroll
                for (int j = 0; j < 4; j++) {
                    ull v = acc[i][j];
                    float lo = fmaxf(__uint_as_float((unsigned)v)         + bv[2 * j],     0.f);
                    float hi = fmaxf(__uint_as_float((unsigned)(v >> 32)) + bv[2 * j + 1], 0.f);
                    dst[j] = pack2(lo, hi);
                }
            }
        }
        wpf0 = *(const float4*)&W2[(size_t)wk0 * DIM + wc0];
        wpf1 = *(const float4*)&W2[(size_t)wk1 * DIM + wc1];
        __syncthreads();   // sH complete

        // ================= GEMM2: C = sH@W2 + b2 =============================
        #pragma unroll
        for (int i = 0; i < 8; i++)
            #pragma unroll
            for (int j = 0; j < 4; j++) acc[i][j] = 0ULL;

        #pragma unroll 1
        for (int k0i = 0; k0i < 8; k0i++) {
            const int k0 = k0i * 16;
            if (k0i > 0) __syncthreads();
            {
                float* d0 = &sW[wk0 * W_STRIDE + widx(wc0)];
                d0[0] = wpf0.x; d0[1] = wpf0.y; d0[2] = wpf0.z; d0[3] = wpf0.w;
                float* d1 = &sW[wk1 * W_STRIDE + widx(wc1)];
                d1[0] = wpf1.x; d1[1] = wpf1.y; d1[2] = wpf1.z; d1[3] = wpf1.w;
                #pragma unroll
                for (int i = 0; i < 8; i++) {
                    int e  = tid + i * 256;
                    int kk = e >> 7;
                    int r  = e & 127;
                    sA2[kk * A2_STRIDE + r] = dup2(sH[r * H_STRIDE + k0 + kk]);
                }
            }
            __syncthreads();
            if (k0i < 7) {
                const int nk0 = k0 + 16;
                wpf0 = *(const float4*)&W2[(size_t)(nk0 + wk0) * DIM + wc0];
                wpf1 = *(const float4*)&W2[(size_t)(nk0 + wk1) * DIM + wc1];
            }
            #pragma unroll
            for (int kk = 0; kk < 16; kk++) {
                ull b2v[4];
                const float* wrow = &sW[kk * W_STRIDE + 10 * tc];
                #pragma unroll
                for (int j = 0; j < 4; j++) b2v[j] = *(const ull*)&wrow[2 * j];
                ull a2[8];
                const ull* arow = &sA2[kk * A2_STRIDE + rbase];
                #pragma unroll
                for (int i = 0; i < 8; i++) a2[i] = arow[i];
                #pragma unroll
                for (int i = 0; i < 8; i++)
                    #pragma unroll
                    for (int j = 0; j < 4; j++)
                        acc[i][j] = ffma2(a2[i], b2v[j], acc[i][j]);
            }
        }

        {
            float bv[8];
            #pragma unroll
            for (int j = 0; j < 8; j++) bv[j] = b2[cbase + j];
            #pragma unroll
            for (int i = 0; i < 8; i++) {
                int r = row0 + rbase + i;
                if (r < N_NODES) {
                    float o[8];
                    #pragma unroll
                    for (int j = 0; j < 4; j++) {
                        ull v = acc[i][j];
                        o[2 * j]     = __uint_as_float((unsigned)v)         + bv[2 * j];
                        o[2 * j + 1] = __uint_as_float((unsigned)(v >> 32)) + bv[2 * j + 1];
                    }
                    *(float4*)&C[(size_t)r * DIM + cbase]     = make_float4(o[0], o[1], o[2], o[3]);
                    *(float4*)&C[(size_t)r * DIM + cbase + 4] = make_float4(o[4], o[5], o[6], o[7]);
                }
            }
        }
    }
}

// ---------------- pooling: batch is sorted -> one block per graph ------------
__global__ void k_pool(const float* __restrict__ x,
                       const int* __restrict__ batch,
                       float* __restrict__ out) {
    int g = blockIdx.x;
    int c = threadIdx.x;
    int a = 0, b = N_NODES;
    while (a < b) { int m = (a + b) >> 1; if (batch[m] < g) a = m + 1; else b = m; }
    int lo = a;
    b = N_NODES;
    while (a < b) { int m = (a + b) >> 1; if (batch[m] < g + 1) a = m + 1; else b = m; }
    int hi = a;
    float s0 = 0.f, s1 = 0.f, s2 = 0.f, s3 = 0.f;
    int i = lo;
    for (; i + 4 <= hi; i += 4) {
        s0 += x[(size_t)(i + 0) * DIM + c];
        s1 += x[(size_t)(i + 1) * DIM + c];
        s2 += x[(size_t)(i + 2) * DIM + c];
        s3 += x[(size_t)(i + 3) * DIM + c];
    }
    for (; i < hi; i++) s0 += x[(size_t)i * DIM + c];
    out[(size_t)g * DIM + c] = (s0 + s1) + (s2 + s3);
}

// ---------------- launch -----------------------------------------------------
extern "C" void kernel_launch(void* const* d_in, const int* in_sizes, int n_in,
                              void* d_out, int out_size) {
    const float* x   = (const float*)d_in[0];
    const int* ei    = (const int*)d_in[1];   // int32 (JAX x64 disabled)
    const int* bat   = (const int*)d_in[2];   // int32
    const float* Ws1 = (const float*)d_in[3];
    const float* bs1 = (const float*)d_in[4];
    const float* Ws2 = (const float*)d_in[5];
    const float* bs2 = (const float*)d_in[6];
    float* out       = (float*)d_out;

    void* p;
    cudaGetSymbolAddress(&p, g_hin);  float* hin = (float*)p;
    cudaGetSymbolAddress(&p, g_xbuf); float* xb  = (float*)p;
    cudaGetSymbolAddress(&p, g_deg);
    cudaMemsetAsync(p, 0, N_NODES * sizeof(int));

    cudaFuncSetAttribute(k_mlp, cudaFuncAttributeMaxDynamicSharedMemorySize, MLP_SMEM);

    k_hist<<<(N_EDGES / 4 + 255) / 256, 256>>>(ei);
    k_scan_part<<<SCAN_BLOCKS, 1024>>>();
    k_scan_add<<<SCAN_BLOCKS, 1024>>>();
    k_scatter<<<(N_EDGES / 4 + 255) / 256, 256>>>(ei);

    const int agg_blocks = (N_NODES * 32 + 63) / 64;
    for (int l = 0; l < N_LAYERS; l++) {
        const float* xin = (l == 0) ? x : xb;
        k_agg<<<agg_blocks, 64>>>(xin, hin);
        k_mlp<<<MLP_GRID, 256, MLP_SMEM>>>(hin,
                                           Ws1 + (size_t)l * DIM * DIM,
                                           bs1 + (size_t)l * DIM,
                                           Ws2 + (size_t)l * DIM * DIM,
                                           bs2 + (size_t)l * DIM,
                                           xb);
    }
    k_pool<<<N_GRAPHS, DIM>>>(xb, bat, out);
}

// round 16
// speedup vs baseline: 1.5348x; 1.0922x over previous
#include <cuda_runtime.h>
#include <cuda_bf16.h>
#include <cstdint>

#define N_NODES 50000
#define N_EDGES 1600000
#define DIM     128
#define N_LAYERS 4
#define N_GRAPHS 512
#define M_TILES  391            // ceil(50000/128)
#define M_PAD    (M_TILES*128)  // 50048
#define SCAN_BLOCKS 49          // 49*1024 >= 50000
#define MLP_GRID 296            // 148 SMs * 2 blocks/SM, persistent

typedef unsigned long long ull;

// ---------------- scratch (static device globals; no allocation) -------------
__device__ int   g_deg[N_NODES];
__device__ int   g_rowstart[N_NODES + 1];
__device__ int   g_cursor[N_NODES];
__device__ int   g_bsum[SCAN_BLOCKS];
__device__ int   g_csr[N_EDGES];
__device__ float g_hin[M_PAD * DIM];   // x + agg (rows >= N_NODES stay 0 forever)
__device__ float g_xbuf[M_PAD * DIM];  // layer output

// ---------------- packed fp32x2 FMA (Blackwell FFMA2) ------------------------
__device__ __forceinline__ ull ffma2(ull a, ull b, ull c) {
    ull d;
    asm("fma.rn.f32x2 %0, %1, %2, %3;" : "=l"(d) : "l"(a), "l"(b), "l"(c));
    return d;
}
__device__ __forceinline__ ull dup2u(unsigned u) {
    ull d;
    asm("mov.b64 %0, {%1, %1};" : "=l"(d) : "r"(u));
    return d;
}
__device__ __forceinline__ ull pack2(float lo, float hi) {
    ull d;
    asm("mov.b64 %0, {%1, %2};" : "=l"(d) : "f"(lo), "f"(hi));
    return d;
}

// ---------------- CSR build --------------------------------------------------
__global__ void k_hist(const int* __restrict__ ei) {
    int t = blockIdx.x * blockDim.x + threadIdx.x;
    if (t < N_EDGES / 4) {
        int4 d = ((const int4*)(ei + N_EDGES))[t];
        atomicAdd(&g_deg[d.x], 1);
        atomicAdd(&g_deg[d.y], 1);
        atomicAdd(&g_deg[d.z], 1);
        atomicAdd(&g_deg[d.w], 1);
    }
}

__global__ void k_scan_part() {
    __shared__ int sh[1024];
    int t = threadIdx.x;
    int i = blockIdx.x * 1024 + t;
    int v = (i < N_NODES) ? g_deg[i] : 0;
    sh[t] = v;
    __syncthreads();
    #pragma unroll
    for (int off = 1; off < 1024; off <<= 1) {
        int u = (t >= off) ? sh[t - off] : 0;
        __syncthreads();
        sh[t] += u;
        __syncthreads();
    }
    if (i < N_NODES) g_rowstart[i] = sh[t] - v;   // local exclusive
    if (t == 1023) g_bsum[blockIdx.x] = sh[1023];
}

__global__ void k_scan_add() {
    __shared__ int sb[SCAN_BLOCKS];
    __shared__ int s_total;
    int t = threadIdx.x;
    if (t < SCAN_BLOCKS) sb[t] = g_bsum[t];
    __syncthreads();
    if (t == 0) {
        int run = 0;
        #pragma unroll 1
        for (int i = 0; i < SCAN_BLOCKS; i++) { int v = sb[i]; sb[i] = run; run += v; }
        s_total = run;
    }
    __syncthreads();
    int off = sb[blockIdx.x];
    int i = blockIdx.x * 1024 + t;
    if (i < N_NODES) {
        int r = g_rowstart[i] + off;
        g_rowstart[i] = r;
        g_cursor[i]   = r;
    }
    if (blockIdx.x == 0 && t == 0) g_rowstart[N_NODES] = s_total;
}

__global__ void k_scatter(const int* __restrict__ ei) {
    int t = blockIdx.x * blockDim.x + threadIdx.x;
    if (t < N_EDGES / 4) {
        int4 s = ((const int4*)ei)[t];
        int4 d = ((const int4*)(ei + N_EDGES))[t];
        g_csr[atomicAdd(&g_cursor[d.x], 1)] = s.x;
        g_csr[atomicAdd(&g_cursor[d.y], 1)] = s.y;
        g_csr[atomicAdd(&g_cursor[d.z], 1)] = s.z;
        g_csr[atomicAdd(&g_cursor[d.w], 1)] = s.w;
    }
}

// ---------------- aggregation: hout[n] = xin[n] + sum_{s in N(n)} xin[s] -----
__global__ __launch_bounds__(64) void k_agg(const float* __restrict__ xin,
                                            float* __restrict__ hout) {
    int warp = (blockIdx.x * blockDim.x + threadIdx.x) >> 5;
    int lane = threadIdx.x & 31;
    if (warp >= N_NODES) return;
    const float4* x4 = (const float4*)xin;
    float4 acc = x4[(size_t)warp * 32 + lane];
    int s = g_rowstart[warp];
    int e = g_rowstart[warp + 1];
    int j = s;
    for (; j + 8 <= e; j += 8) {
        int idx[8];
        #pragma unroll
        for (int t = 0; t < 8; t++) idx[t] = __ldg(&g_csr[j + t]);
        float4 v[8];
        #pragma unroll
        for (int t = 0; t < 8; t++) v[t] = __ldg(&x4[(size_t)idx[t] * 32 + lane]);
        #pragma unroll
        for (int t = 0; t < 8; t++) {
            acc.x += v[t].x; acc.y += v[t].y; acc.z += v[t].z; acc.w += v[t].w;
        }
    }
    for (; j < e; j++) {
        int src = __ldg(&g_csr[j]);
        float4 v = __ldg(&x4[(size_t)src * 32 + lane]);
        acc.x += v.x; acc.y += v.y; acc.z += v.z; acc.w += v.w;
    }
    ((float4*)hout)[(size_t)warp * 32 + lane] = acc;
}

// ---------------- fused MLP (persistent, broadcast-A): ----------------------
// C = relu(A@W1+b1)@W2 + b2
// smem: sAH [128][132] f32  row-major A tile (stride mult of 4 -> float4 ok);
//                           overwritten by H after GEMM1
//       sW  [2][16][160] f32 double-buffered W tile (conflict-free col pairs)
#define AH_STRIDE 132
#define W_STRIDE  160
#define WT_FLOATS (16 * W_STRIDE)                  // 2560 per buffer
#define OFF_Wf    (128 * AH_STRIDE)                // 16896 floats
#define MLP_SMEM  ((OFF_Wf + 2 * WT_FLOATS) * 4)   // 88,064 B

__device__ __forceinline__ int widx(int c) { return c + ((c >> 3) << 1); }

__global__ __launch_bounds__(256, 2) void k_mlp(const float* __restrict__ A,
                                                const float* __restrict__ W1,
                                                const float* __restrict__ b1,
                                                const float* __restrict__ W2,
                                                const float* __restrict__ b2,
                                                float* __restrict__ C) {
    extern __shared__ __align__(16) float smem[];
    float* sAH = smem;
    float* sW  = smem + OFF_Wf;

    const int tid  = threadIdx.x;
    const int tr = tid >> 4;        // 0..15
    const int tc = tid & 15;        // 0..15
    const int rbase = tr * 8;
    const int cbase = tc * 8;

    const int wk0 = (tid * 2) >> 5,       wc0 = ((tid * 2) & 31) * 4;
    const int wk1 = (tid * 2 + 1) >> 5,   wc1 = ((tid * 2 + 1) & 31) * 4;

    for (int tile = blockIdx.x; tile < M_TILES; tile += gridDim.x) {
        const int row0 = tile * 128;
        ull acc[8][4];

        // ---- stage full A tile once (row-major, coalesced) ----
        __syncthreads();   // previous tile's GEMM2 reads of sAH complete
        #pragma unroll
        for (int it = 0; it < 16; it++) {
            int idx = tid + it * 256;        // 0..4095 float4
            int r = idx >> 5;                // 0..127
            int c = (idx & 31) * 4;          // 0..124
            float4 v = *(const float4*)&A[(size_t)(row0 + r) * DIM + c];
            *(float4*)&sAH[r * AH_STRIDE + c] = v;
        }

        float4 wpf0 = *(const float4*)&W1[(size_t)wk0 * DIM + wc0];
        float4 wpf1 = *(const float4*)&W1[(size_t)wk1 * DIM + wc1];

        // ================= GEMM1: acc = A@W1 =================================
        #pragma unroll
        for (int i = 0; i < 8; i++)
            #pragma unroll
            for (int j = 0; j < 4; j++) acc[i][j] = 0ULL;

        #pragma unroll 1
        for (int k0i = 0; k0i < 8; k0i++) {
            const int k0 = k0i * 16;
            float* sWb = sW + (k0i & 1) * WT_FLOATS;
            {
                float* d0 = &sWb[wk0 * W_STRIDE + widx(wc0)];
                d0[0] = wpf0.x; d0[1] = wpf0.y; d0[2] = wpf0.z; d0[3] = wpf0.w;
                float* d1 = &sWb[wk1 * W_STRIDE + widx(wc1)];
                d1[0] = wpf1.x; d1[1] = wpf1.y; d1[2] = wpf1.z; d1[3] = wpf1.w;
            }
            __syncthreads();   // A tile (k0i==0) + this W buffer visible
            if (k0i < 7) {
                const int nk0 = k0 + 16;
                wpf0 = *(const float4*)&W1[(size_t)(nk0 + wk0) * DIM + wc0];
                wpf1 = *(const float4*)&W1[(size_t)(nk0 + wk1) * DIM + wc1];
            }
            #pragma unroll
            for (int m = 0; m < 8; m++) {   // two kk per m
                ull apair[8];
                #pragma unroll
                for (int i = 0; i < 8; i++)
                    apair[i] = *(const ull*)&sAH[(rbase + i) * AH_STRIDE + k0 + 2 * m];
                #pragma unroll
                for (int half = 0; half < 2; half++) {
                    const int kk = 2 * m + half;
                    ull b2v[4];
                    const float* wrow = &sWb[kk * W_STRIDE + 10 * tc];
                    #pragma unroll
                    for (int j = 0; j < 4; j++) b2v[j] = *(const ull*)&wrow[2 * j];
                    #pragma unroll
                    for (int i = 0; i < 8; i++) {
                        unsigned av = half ? (unsigned)(apair[i] >> 32)
                                           : (unsigned)apair[i];
                        ull a2 = dup2u(av);
                        #pragma unroll
                        for (int j = 0; j < 4; j++)
                            acc[i][j] = ffma2(a2, b2v[j], acc[i][j]);
                    }
                }
            }
        }

        // ---- epilogue 1: H = relu(acc + b1) -> sAH (in place) ----
        __syncthreads();   // all threads done reading sAH as A
        {
            float bv[8];
            #pragma unroll
            for (int j = 0; j < 8; j++) bv[j] = b1[cbase + j];
            #pragma unroll
            for (int i = 0; i < 8; i++) {
                ull* dst = (ull*)&sAH[(rbase + i) * AH_STRIDE + cbase];
                #pragma unroll
                for (int j = 0; j < 4; j++) {
                    ull v = acc[i][j];
                    float lo = fmaxf(__uint_as_float((unsigned)v)         + bv[2 * j],     0.f);
                    float hi = fmaxf(__uint_as_float((unsigned)(v >> 32)) + bv[2 * j + 1], 0.f);
                    dst[j] = pack2(lo, hi);
                }
            }
        }
        wpf0 = *(const float4*)&W2[(size_t)wk0 * DIM + wc0];
        wpf1 = *(const float4*)&W2[(size_t)wk1 * DIM + wc1];
        __syncthreads();   // H complete

        // ================= GEMM2: acc = H@W2 =================================
        #pragma unroll
        for (int i = 0; i < 8; i++)
            #pragma unroll
            for (int j = 0; j < 4; j++) acc[i][j] = 0ULL;

        #pragma unroll 1
        for (int k0i = 0; k0i < 8; k0i++) {
            const int k0 = k0i * 16;
            float* sWb = sW + (k0i & 1) * WT_FLOATS;
            {
                float* d0 = &sWb[wk0 * W_STRIDE + widx(wc0)];
                d0[0] = wpf0.x; d0[1] = wpf0.y; d0[2] = wpf0.z; d0[3] = wpf0.w;
                float* d1 = &sWb[wk1 * W_STRIDE + widx(wc1)];
                d1[0] = wpf1.x; d1[1] = wpf1.y; d1[2] = wpf1.z; d1[3] = wpf1.w;
            }
            __syncthreads();
            if (k0i < 7) {
                const int nk0 = k0 + 16;
                wpf0 = *(const float4*)&W2[(size_t)(nk0 + wk0) * DIM + wc0];
                wpf1 = *(const float4*)&W2[(size_t)(nk0 + wk1) * DIM + wc1];
            }
            #pragma unroll
            for (int m = 0; m < 8; m++) {
                ull apair[8];
                #pragma unroll
                for (int i = 0; i < 8; i++)
                    apair[i] = *(const ull*)&sAH[(rbase + i) * AH_STRIDE + k0 + 2 * m];
                #pragma unroll
                for (int half = 0; half < 2; half++) {
                    const int kk = 2 * m + half;
                    ull b2v[4];
                    const float* wrow = &sWb[kk * W_STRIDE + 10 * tc];
                    #pragma unroll
                    for (int j = 0; j < 4; j++) b2v[j] = *(const ull*)&wrow[2 * j];
                    #pragma unroll
                    for (int i = 0; i < 8; i++) {
                        unsigned av = half ? (unsigned)(apair[i] >> 32)
                                           : (unsigned)apair[i];
                        ull a2 = dup2u(av);
                        #pragma unroll
                        for (int j = 0; j < 4; j++)
                            acc[i][j] = ffma2(a2, b2v[j], acc[i][j]);
                    }
                }
            }
        }

        // ---- epilogue 2: C = acc + b2 -> global (guarded) ----
        {
            float bv[8];
            #pragma unroll
            for (int j = 0; j < 8; j++) bv[j] = b2[cbase + j];
            #pragma unroll
            for (int i = 0; i < 8; i++) {
                int r = row0 + rbase + i;
                if (r < N_NODES) {
                    float o[8];
                    #pragma unroll
                    for (int j = 0; j < 4; j++) {
                        ull v = acc[i][j];
                        o[2 * j]     = __uint_as_float((unsigned)v)         + bv[2 * j];
                        o[2 * j + 1] = __uint_as_float((unsigned)(v >> 32)) + bv[2 * j + 1];
                    }
                    *(float4*)&C[(size_t)r * DIM + cbase]     = make_float4(o[0], o[1], o[2], o[3]);
                    *(float4*)&C[(size_t)r * DIM + cbase + 4] = make_float4(o[4], o[5], o[6], o[7]);
                }
            }
        }
    }
}

// ---------------- pooling: batch is sorted -> one block per graph ------------
__global__ void k_pool(const float* __restrict__ x,
                       const int* __restrict__ batch,
                       float* __restrict__ out) {
    int g = blockIdx.x;
    int c = threadIdx.x;
    int a = 0, b = N_NODES;
    while (a < b) { int m = (a + b) >> 1; if (batch[m] < g) a = m + 1; else b = m; }
    int lo = a;
    b = N_NODES;
    while (a < b) { int m = (a + b) >> 1; if (batch[m] < g + 1) a = m + 1; else b = m; }
    int hi = a;
    float s0 = 0.f, s1 = 0.f, s2 = 0.f, s3 = 0.f;
    int i = lo;
    for (; i + 4 <= hi; i += 4) {
        s0 += x[(size_t)(i + 0) * DIM + c];
        s1 += x[(size_t)(i + 1) * DIM + c];
        s2 += x[(size_t)(i + 2) * DIM + c];
        s3 += x[(size_t)(i + 3) * DIM + c];
    }
    for (; i < hi; i++) s0 += x[(size_t)i * DIM + c];
    out[(size_t)g * DIM + c] = (s0 + s1) + (s2 + s3);
}

// ---------------- launch -----------------------------------------------------
extern "C" void kernel_launch(void* const* d_in, const int* in_sizes, int n_in,
                              void* d_out, int out_size) {
    const float* x   = (const float*)d_in[0];
    const int* ei    = (const int*)d_in[1];   // int32 (JAX x64 disabled)
    const int* bat   = (const int*)d_in[2];   // int32
    const float* Ws1 = (const float*)d_in[3];
    const float* bs1 = (const float*)d_in[4];
    const float* Ws2 = (const float*)d_in[5];
    const float* bs2 = (const float*)d_in[6];
    float* out       = (float*)d_out;

    void* p;
    cudaGetSymbolAddress(&p, g_hin);  float* hin = (float*)p;
    cudaGetSymbolAddress(&p, g_xbuf); float* xb  = (float*)p;
    cudaGetSymbolAddress(&p, g_deg);
    cudaMemsetAsync(p, 0, N_NODES * sizeof(int));

    cudaFuncSetAttribute(k_mlp, cudaFuncAttributeMaxDynamicSharedMemorySize, MLP_SMEM);

    k_hist<<<(N_EDGES / 4 + 255) / 256, 256>>>(ei);
    k_scan_part<<<SCAN_BLOCKS, 1024>>>();
    k_scan_add<<<SCAN_BLOCKS, 1024>>>();
    k_scatter<<<(N_EDGES / 4 + 255) / 256, 256>>>(ei);

    const int agg_blocks = (N_NODES * 32 + 63) / 64;
    for (int l = 0; l < N_LAYERS; l++) {
        const float* xin = (l == 0) ? x : xb;
        k_agg<<<agg_blocks, 64>>>(xin, hin);
        k_mlp<<<MLP_GRID, 256, MLP_SMEM>>>(hin,
                                           Ws1 + (size_t)l * DIM * DIM,
                                           bs1 + (size_t)l * DIM,
                                           Ws2 + (size_t)l * DIM * DIM,
                                           bs2 + (size_t)l * DIM,
                                           xb);
    }
    k_pool<<<N_GRAPHS, DIM>>>(xb, bat, out);
}